// round 7
// baseline (speedup 1.0000x reference)
#include <cuda_runtime.h>
#include <cstdint>

#define NN 100000
#define EE 1600000
#define EA 7
#define HH 64
#define LL 32
#define GG 512
#define CC 6

// ---------------- scratch (static device globals: no allocation) -------------
__device__ float g_agg1[NN];
__device__ float g_h1[(size_t)NN * HH];
__device__ float g_agg2[(size_t)NN * HH];
__device__ float g_h2[(size_t)NN * HH];
__device__ float g_zsum[GG * LL];
__device__ float g_cnt[GG];

// ---------------- JAX threefry2x32-20 + normal ------------------------------
__device__ __forceinline__ void tf_round(uint32_t& x0, uint32_t& x1, int r) {
    x0 += x1;
    x1 = (x1 << r) | (x1 >> (32 - r));
    x1 ^= x0;
}

__device__ __forceinline__ void threefry2x32(uint32_t k0, uint32_t k1,
                                             uint32_t c0, uint32_t c1,
                                             uint32_t& o0, uint32_t& o1) {
    uint32_t ks2 = k0 ^ k1 ^ 0x1BD11BDAu;
    uint32_t x0 = c0 + k0, x1 = c1 + k1;
    tf_round(x0,x1,13); tf_round(x0,x1,15); tf_round(x0,x1,26); tf_round(x0,x1,6);
    x0 += k1;  x1 += ks2 + 1u;
    tf_round(x0,x1,17); tf_round(x0,x1,29); tf_round(x0,x1,16); tf_round(x0,x1,24);
    x0 += ks2; x1 += k0 + 2u;
    tf_round(x0,x1,13); tf_round(x0,x1,15); tf_round(x0,x1,26); tf_round(x0,x1,6);
    x0 += k0;  x1 += k1 + 3u;
    tf_round(x0,x1,17); tf_round(x0,x1,29); tf_round(x0,x1,16); tf_round(x0,x1,24);
    x0 += k1;  x1 += ks2 + 4u;
    tf_round(x0,x1,13); tf_round(x0,x1,15); tf_round(x0,x1,26); tf_round(x0,x1,6);
    x0 += ks2; x1 += k0 + 5u;
    o0 = x0; o1 = x1;
}

// noise[flat] for jax.random.normal(key(42), (N,32), f32), PARTITIONABLE threefry:
// each element i drawn from counter (hi=i>>32=0, lo=i); 32-bit draw = x0 ^ x1.
__device__ __forceinline__ float jax_normal_42(uint32_t flat) {
    uint32_t o0, o1;
    threefry2x32(0u, 42u, 0u, flat, o0, o1);
    uint32_t bits = o0 ^ o1;
    float f = __uint_as_float((bits >> 9) | 0x3F800000u) - 1.0f;   // [0,1)
    const float lo = -0.99999994f;                                 // nextafter(-1,0)
    float u = fmaf(f, 1.0f - lo, lo);
    u = fmaxf(u, lo);
    return 1.41421356f * erfinvf(u);                               // sqrt(2)*erfinv
}

// ---------------- kernels ----------------------------------------------------

__global__ __launch_bounds__(256) void k_zero() {
    int i = blockIdx.x * 256 + threadIdx.x;                 // grid covers 6.4M
    if (i < NN * HH) g_agg2[i] = 0.f;
    if (i < NN)      g_agg1[i] = 0.f;
    if (i < GG * LL) g_zsum[i] = 0.f;
    if (i < GG)      g_cnt[i]  = 0.f;
}

// edge pass 1 (scalar features)
__global__ __launch_bounds__(256) void k_edge1(const float* __restrict__ x,
                                               const int*   __restrict__ ei,
                                               const float* __restrict__ eattr,
                                               const float* __restrict__ We1,
                                               const float* __restrict__ be1) {
    int e = blockIdx.x * 256 + threadIdx.x;
    if (e >= EE) return;
    int s = ei[e], d = ei[EE + e];
    const float* ea = eattr + (size_t)e * EA;
    float v = be1[0];
#pragma unroll
    for (int a = 0; a < EA; a++) v = fmaf(__ldg(ea + a), __ldg(We1 + a), v);
    float m = fmaxf(x[s] + v, 0.f);
    atomicAdd(&g_agg1[d], m);
}

// node MLP 1: scalar -> H -> H ; h1 = relu(relu(hpre*W11+b11)@W12+b12)
__global__ __launch_bounds__(256) void k_mlp1(const float* __restrict__ x,
                                              const float* __restrict__ W11,
                                              const float* __restrict__ b11,
                                              const float* __restrict__ W12,
                                              const float* __restrict__ b12,
                                              const float* __restrict__ eps1) {
    __shared__ float sW12[HH * HH];
    __shared__ float sW11[HH], sb11[HH], sb12[HH];
    __shared__ float st[4][HH];
    int tid = threadIdx.x;
    for (int i = tid; i < HH * HH; i += 256) sW12[i] = W12[i];
    if (tid < HH) { sW11[tid] = W11[tid]; sb11[tid] = b11[tid]; sb12[tid] = b12[tid]; }
    __syncthreads();
    float epsv = 1.0f + eps1[0];
    int i = tid & 63, loc = tid >> 6;
    for (int g = 0; g < 8; g++) {
        int node = (blockIdx.x * 8 + g) * 4 + loc;          // 3125*8*4 = 100000 exact
        float hpre = fmaf(epsv, x[node], g_agg1[node]);
        st[loc][i] = fmaxf(fmaf(hpre, sW11[i], sb11[i]), 0.f);
        __syncthreads();
        float acc = sb12[i];
#pragma unroll
        for (int j = 0; j < HH; j++) acc = fmaf(st[loc][j], sW12[j * HH + i], acc);
        g_h1[(size_t)node * HH + i] = fmaxf(acc, 0.f);
        __syncthreads();
    }
}

// edge pass 2 (H features). 256 thr = 4 edges/iter, 16 iters = 64 edges/block.
__global__ __launch_bounds__(256) void k_edge2(const int*   __restrict__ ei,
                                               const float* __restrict__ eattr,
                                               const float* __restrict__ We2,
                                               const float* __restrict__ be2) {
    int j = threadIdx.x & 63;
    int eloc = threadIdx.x >> 6;
    float rWe[EA];
#pragma unroll
    for (int a = 0; a < EA; a++) rWe[a] = __ldg(We2 + a * HH + j);
    float rbe = __ldg(be2 + j);
    size_t base = (size_t)blockIdx.x * 64;
#pragma unroll 2
    for (int it = 0; it < 16; it++) {
        size_t e = base + (size_t)it * 4 + eloc;            // 25000*64 = 1.6M exact
        int s = ei[e], d = ei[EE + e];
        const float* ea = eattr + e * EA;
        float v = rbe;
#pragma unroll
        for (int a = 0; a < EA; a++) v = fmaf(__ldg(ea + a), rWe[a], v);
        float m = fmaxf(g_h1[(size_t)s * HH + j] + v, 0.f);
        atomicAdd(&g_agg2[(size_t)d * HH + j], m);
    }
}

// node MLP 2: H -> H -> H
__global__ __launch_bounds__(256) void k_mlp2(const float* __restrict__ W21,
                                              const float* __restrict__ b21,
                                              const float* __restrict__ W22,
                                              const float* __restrict__ b22,
                                              const float* __restrict__ eps2) {
    __shared__ float sW21[HH * HH], sW22[HH * HH];
    __shared__ float sb21[HH], sb22[HH];
    __shared__ float sh[4][HH], st[4][HH];
    int tid = threadIdx.x;
    for (int i = tid; i < HH * HH; i += 256) { sW21[i] = W21[i]; sW22[i] = W22[i]; }
    if (tid < HH) { sb21[tid] = b21[tid]; sb22[tid] = b22[tid]; }
    __syncthreads();
    float epsv = 1.0f + eps2[0];
    int i = tid & 63, loc = tid >> 6;
    for (int g = 0; g < 8; g++) {
        int node = (blockIdx.x * 8 + g) * 4 + loc;
        size_t off = (size_t)node * HH + i;
        sh[loc][i] = fmaf(epsv, g_h1[off], g_agg2[off]);
        __syncthreads();
        float acc = sb21[i];
#pragma unroll
        for (int j = 0; j < HH; j++) acc = fmaf(sh[loc][j], sW21[j * HH + i], acc);
        st[loc][i] = fmaxf(acc, 0.f);
        __syncthreads();
        acc = sb22[i];
#pragma unroll
        for (int j = 0; j < HH; j++) acc = fmaf(st[loc][j], sW22[j * HH + i], acc);
        g_h2[off] = fmaxf(acc, 0.f);
        __syncthreads();
    }
}

// heads: mu/logvar/z + per-graph pooled sums. 256 thr = 8 nodes x 32 lanes.
__global__ __launch_bounds__(256) void k_heads(const float* __restrict__ Wmu,
                                               const float* __restrict__ bmu,
                                               const float* __restrict__ Wlv,
                                               const float* __restrict__ blv,
                                               const int*   __restrict__ batch,
                                               float* __restrict__ out) {
    __shared__ float sWmu[HH * LL], sWlv[HH * LL];
    __shared__ float sbmu[LL], sblv[LL];
    __shared__ float sh2[8][HH];
    int tid = threadIdx.x;
    for (int i = tid; i < HH * LL; i += 256) { sWmu[i] = Wmu[i]; sWlv[i] = Wlv[i]; }
    if (tid < LL) { sbmu[tid] = bmu[tid]; sblv[tid] = blv[tid]; }
    __syncthreads();
    int l = tid & 31, loc = tid >> 5;
    float* out_z  = out;
    float* out_mu = out + (size_t)NN * LL;
    float* out_lv = out + (size_t)2 * NN * LL;
    for (int it = 0; it < 8; it++) {
        int node = blockIdx.x * 64 + it * 8 + loc;
        if (node < NN) {
            sh2[loc][l]      = g_h2[(size_t)node * HH + l];
            sh2[loc][l + 32] = g_h2[(size_t)node * HH + l + 32];
        }
        __syncthreads();
        if (node < NN) {
            float mu = sbmu[l], lv = sblv[l];
#pragma unroll
            for (int k = 0; k < HH; k++) {
                float h = sh2[loc][k];
                mu = fmaf(h, sWmu[k * LL + l], mu);
                lv = fmaf(h, sWlv[k * LL + l], lv);
            }
            uint32_t flat = (uint32_t)node * LL + (uint32_t)l;
            float nz = jax_normal_42(flat);
            float z = fmaf(nz, expf(0.5f * lv), mu);
            out_z[flat]  = z;
            out_mu[flat] = mu;
            out_lv[flat] = lv;
            int b = batch[node];
            atomicAdd(&g_zsum[b * LL + l], z);
            if (l == 0) atomicAdd(&g_cnt[b], 1.0f);
        }
        __syncthreads();
    }
}

__global__ __launch_bounds__(256) void k_logits(const float* __restrict__ Wc,
                                                const float* __restrict__ bc,
                                                float* __restrict__ out) {
    int g = blockIdx.x * 256 + threadIdx.x;
    if (g >= GG) return;
    float inv = 1.0f / fmaxf(g_cnt[g], 1.0f);
    float acc[CC];
#pragma unroll
    for (int c = 0; c < CC; c++) acc[c] = bc[c];
#pragma unroll
    for (int l = 0; l < LL; l++) {
        float v = g_zsum[g * LL + l] * inv;
#pragma unroll
        for (int c = 0; c < CC; c++) acc[c] = fmaf(v, Wc[l * CC + c], acc[c]);
    }
    float* out_lg = out + (size_t)3 * NN * LL;
#pragma unroll
    for (int c = 0; c < CC; c++) out_lg[(size_t)g * CC + c] = acc[c];
}

// ---------------- launch -----------------------------------------------------
extern "C" void kernel_launch(void* const* d_in, const int* in_sizes, int n_in,
                              void* d_out, int out_size) {
    const float* x     = (const float*)d_in[0];
    const int*   ei    = (const int*)  d_in[1];   // [2,E] (jax default -> int32)
    const float* eattr = (const float*)d_in[2];
    const int*   batch = (const int*)  d_in[3];
    const float* We1  = (const float*)d_in[4];
    const float* be1  = (const float*)d_in[5];
    const float* W11  = (const float*)d_in[6];
    const float* b11  = (const float*)d_in[7];
    const float* W12  = (const float*)d_in[8];
    const float* b12  = (const float*)d_in[9];
    const float* eps1 = (const float*)d_in[10];
    const float* We2  = (const float*)d_in[11];
    const float* be2  = (const float*)d_in[12];
    const float* W21  = (const float*)d_in[13];
    const float* b21  = (const float*)d_in[14];
    const float* W22  = (const float*)d_in[15];
    const float* b22  = (const float*)d_in[16];
    const float* eps2 = (const float*)d_in[17];
    const float* Wmu  = (const float*)d_in[18];
    const float* bmu  = (const float*)d_in[19];
    const float* Wlv  = (const float*)d_in[20];
    const float* blv  = (const float*)d_in[21];
    const float* Wc   = (const float*)d_in[22];
    const float* bc   = (const float*)d_in[23];
    float* out = (float*)d_out;

    k_zero  <<<(NN * HH) / 256, 256>>>();                       // 25000 blocks
    k_edge1 <<<(EE + 255) / 256, 256>>>(x, ei, eattr, We1, be1);
    k_mlp1  <<<NN / 32, 256>>>(x, W11, b11, W12, b12, eps1);    // 3125 blocks
    k_edge2 <<<EE / 64, 256>>>(ei, eattr, We2, be2);            // 25000 blocks
    k_mlp2  <<<NN / 32, 256>>>(W21, b21, W22, b22, eps2);       // 3125 blocks
    k_heads <<<(NN + 63) / 64, 256>>>(Wmu, bmu, Wlv, blv, batch, out);
    k_logits<<<(GG + 255) / 256, 256>>>(Wc, bc, out);
}

// round 9
// speedup vs baseline: 1.3505x; 1.3505x over previous
#include <cuda_runtime.h>
#include <cstdint>

#define NN 100000
#define EE 1600000
#define EA 7
#define HH 64
#define LL 32
#define GG 512
#define CC 6

// ---------------- scratch (static device globals: no allocation) -------------
__device__ float g_agg1[NN];
__device__ float g_h1[(size_t)NN * HH];
__device__ float g_agg2[(size_t)NN * HH];
__device__ float g_h2[(size_t)NN * HH];
__device__ float g_zsum[GG * LL];
__device__ float g_cnt[GG];

// ---------------- f32x2 / vector-red helpers ---------------------------------
typedef unsigned long long u64;
__device__ __forceinline__ u64 pack2f(float x, float y) {
    u64 r; asm("mov.b64 %0,{%1,%2};" : "=l"(r) : "f"(x), "f"(y)); return r;
}
__device__ __forceinline__ u64 pack2(float x) {
    u64 r; asm("mov.b64 %0,{%1,%1};" : "=l"(r) : "f"(x)); return r;
}
__device__ __forceinline__ float2 unpack2(u64 v) {
    float2 f; asm("mov.b64 {%0,%1},%2;" : "=f"(f.x), "=f"(f.y) : "l"(v)); return f;
}
__device__ __forceinline__ u64 fma2(u64 a, u64 b, u64 c) {
    u64 d; asm("fma.rn.f32x2 %0,%1,%2,%3;" : "=l"(d) : "l"(a), "l"(b), "l"(c)); return d;
}
__device__ __forceinline__ void red4(float* p, float4 v) {
    asm volatile("red.global.add.v4.f32 [%0],{%1,%2,%3,%4};"
                 :: "l"(p), "f"(v.x), "f"(v.y), "f"(v.z), "f"(v.w) : "memory");
}
__device__ __forceinline__ void red2(float* p, float2 v) {
    asm volatile("red.global.add.v2.f32 [%0],{%1,%2};"
                 :: "l"(p), "f"(v.x), "f"(v.y) : "memory");
}

// ---------------- JAX threefry2x32-20 (partitionable) + normal ----------------
__device__ __forceinline__ void tf_round(uint32_t& x0, uint32_t& x1, int r) {
    x0 += x1;
    x1 = (x1 << r) | (x1 >> (32 - r));
    x1 ^= x0;
}
__device__ __forceinline__ void threefry2x32(uint32_t k0, uint32_t k1,
                                             uint32_t c0, uint32_t c1,
                                             uint32_t& o0, uint32_t& o1) {
    uint32_t ks2 = k0 ^ k1 ^ 0x1BD11BDAu;
    uint32_t x0 = c0 + k0, x1 = c1 + k1;
    tf_round(x0,x1,13); tf_round(x0,x1,15); tf_round(x0,x1,26); tf_round(x0,x1,6);
    x0 += k1;  x1 += ks2 + 1u;
    tf_round(x0,x1,17); tf_round(x0,x1,29); tf_round(x0,x1,16); tf_round(x0,x1,24);
    x0 += ks2; x1 += k0 + 2u;
    tf_round(x0,x1,13); tf_round(x0,x1,15); tf_round(x0,x1,26); tf_round(x0,x1,6);
    x0 += k0;  x1 += k1 + 3u;
    tf_round(x0,x1,17); tf_round(x0,x1,29); tf_round(x0,x1,16); tf_round(x0,x1,24);
    x0 += k1;  x1 += ks2 + 4u;
    tf_round(x0,x1,13); tf_round(x0,x1,15); tf_round(x0,x1,26); tf_round(x0,x1,6);
    x0 += ks2; x1 += k0 + 5u;
    o0 = x0; o1 = x1;
}
__device__ __forceinline__ float jax_normal_42(uint32_t flat) {
    uint32_t o0, o1;
    threefry2x32(0u, 42u, 0u, flat, o0, o1);
    uint32_t bits = o0 ^ o1;
    float f = __uint_as_float((bits >> 9) | 0x3F800000u) - 1.0f;   // [0,1)
    const float lo = -0.99999994f;
    float u = fmaf(f, 1.0f - lo, lo);
    u = fmaxf(u, lo);
    return 1.41421356f * erfinvf(u);
}

// ---------------- kernels ----------------------------------------------------

__global__ __launch_bounds__(256) void k_zero() {            // grid 6250
    int i = blockIdx.x * 256 + threadIdx.x;                  // float4 index
    ((float4*)g_agg2)[i] = make_float4(0.f, 0.f, 0.f, 0.f);
    if (i < NN / 4)      ((float4*)g_agg1)[i] = make_float4(0.f, 0.f, 0.f, 0.f);
    if (i < GG * LL / 4) ((float4*)g_zsum)[i] = make_float4(0.f, 0.f, 0.f, 0.f);
    if (i < GG / 4)      ((float4*)g_cnt)[i]  = make_float4(0.f, 0.f, 0.f, 0.f);
}

// edge pass 1 (scalar features); eattr staged via smem. 256 edges/block.
__global__ __launch_bounds__(256) void k_edge1(const float* __restrict__ x,
                                               const int*   __restrict__ ei,
                                               const float* __restrict__ eattr,
                                               const float* __restrict__ We1,
                                               const float* __restrict__ be1) {
    __shared__ float sea[256 * EA];
    int tid = threadIdx.x;
    size_t base = (size_t)blockIdx.x * 256;
    for (int i = tid; i < 256 * EA; i += 256) sea[i] = eattr[base * EA + i];
    float rW[EA];
#pragma unroll
    for (int a = 0; a < EA; a++) rW[a] = __ldg(We1 + a);
    float rbe = __ldg(be1);
    __syncthreads();
    size_t e = base + tid;
    int s = ei[e], d = ei[EE + e];
    float v = rbe;
#pragma unroll
    for (int a = 0; a < EA; a++) v = fmaf(sea[tid * EA + a], rW[a], v);
    float m = fmaxf(x[s] + v, 0.f);
    atomicAdd(&g_agg1[d], m);
}

// node MLP 1: 16 thr/node, 80 nodes/block (grid 1250)
__global__ __launch_bounds__(256) void k_mlp1(const float* __restrict__ x,
                                              const float* __restrict__ W11,
                                              const float* __restrict__ b11,
                                              const float* __restrict__ W12,
                                              const float* __restrict__ b12,
                                              const float* __restrict__ eps1) {
    __shared__ float sW12[HH * HH];
    __shared__ float sW11[HH], sb11[HH], sb12[HH];
    __shared__ float st[16][HH];
    int tid = threadIdx.x;
    for (int i = tid; i < HH * HH; i += 256) sW12[i] = W12[i];
    if (tid < HH) { sW11[tid] = W11[tid]; sb11[tid] = b11[tid]; sb12[tid] = b12[tid]; }
    __syncthreads();
    float epsv = 1.0f + __ldg(eps1);
    int q = tid & 15, nl = tid >> 4;
    int base = blockIdx.x * 80;
#pragma unroll
    for (int it = 0; it < 5; it++) {
        int node = base + it * 16 + nl;
        float hpre = fmaf(epsv, __ldg(x + node), g_agg1[node]);
        float4 w = *(const float4*)&sW11[q * 4];
        float4 b = *(const float4*)&sb11[q * 4];
        float4 t;
        t.x = fmaxf(fmaf(hpre, w.x, b.x), 0.f);
        t.y = fmaxf(fmaf(hpre, w.y, b.y), 0.f);
        t.z = fmaxf(fmaf(hpre, w.z, b.z), 0.f);
        t.w = fmaxf(fmaf(hpre, w.w, b.w), 0.f);
        *(float4*)&st[nl][q * 4] = t;
        __syncwarp();
        u64 a0 = pack2f(sb12[q * 4], sb12[q * 4 + 1]);
        u64 a1 = pack2f(sb12[q * 4 + 2], sb12[q * 4 + 3]);
#pragma unroll
        for (int j = 0; j < HH; j++) {
            u64 s2 = pack2(st[nl][j]);
            ulonglong2 wv = *(const ulonglong2*)&sW12[j * HH + q * 4];
            a0 = fma2(wv.x, s2, a0);
            a1 = fma2(wv.y, s2, a1);
        }
        float2 lo = unpack2(a0), hi = unpack2(a1);
        float4 o;
        o.x = fmaxf(lo.x, 0.f); o.y = fmaxf(lo.y, 0.f);
        o.z = fmaxf(hi.x, 0.f); o.w = fmaxf(hi.y, 0.f);
        *(float4*)(g_h1 + (size_t)node * HH + q * 4) = o;
        __syncwarp();
    }
}

// edge pass 2: 128 edges/block (grid 12500), 16 thr/edge, float4 + red.v4
__global__ __launch_bounds__(256) void k_edge2(const int*   __restrict__ ei,
                                               const float* __restrict__ eattr,
                                               const float* __restrict__ We2,
                                               const float* __restrict__ be2) {
    __shared__ float sea[128 * EA];
    __shared__ int   ss[128], sd[128];
    int tid = threadIdx.x;
    size_t base = (size_t)blockIdx.x * 128;
    for (int i = tid; i < 128 * EA; i += 256) sea[i] = eattr[base * EA + i];
    if (tid < 128)       ss[tid] = ei[base + tid];
    else                 sd[tid - 128] = ei[EE + base + (tid - 128)];
    int q = tid & 15, el = tid >> 4;
    ulonglong2 rw[EA];
#pragma unroll
    for (int a = 0; a < EA; a++) {
        float4 w = __ldg((const float4*)(We2 + a * HH + q * 4));
        rw[a].x = pack2f(w.x, w.y);
        rw[a].y = pack2f(w.z, w.w);
    }
    float4 rb = __ldg((const float4*)(be2 + q * 4));
    u64 rb0 = pack2f(rb.x, rb.y), rb1 = pack2f(rb.z, rb.w);
    __syncthreads();
#pragma unroll 2
    for (int sub = 0; sub < 8; sub++) {
        int e = sub * 16 + el;
        int s = ss[e], d = sd[e];
        float4 h = __ldg((const float4*)(g_h1 + (size_t)s * HH + q * 4));
        u64 v0 = rb0, v1 = rb1;
#pragma unroll
        for (int a = 0; a < EA; a++) {
            u64 ea2 = pack2(sea[e * EA + a]);
            v0 = fma2(rw[a].x, ea2, v0);
            v1 = fma2(rw[a].y, ea2, v1);
        }
        float2 lo = unpack2(v0), hi = unpack2(v1);
        float4 m;
        m.x = fmaxf(h.x + lo.x, 0.f);
        m.y = fmaxf(h.y + lo.y, 0.f);
        m.z = fmaxf(h.z + hi.x, 0.f);
        m.w = fmaxf(h.w + hi.y, 0.f);
        red4(g_agg2 + (size_t)d * HH + q * 4, m);
    }
}

// node MLP 2: 16 thr/node, 80 nodes/block (grid 1250), f32x2 inner loops
__global__ __launch_bounds__(256) void k_mlp2(const float* __restrict__ W21,
                                              const float* __restrict__ b21,
                                              const float* __restrict__ W22,
                                              const float* __restrict__ b22,
                                              const float* __restrict__ eps2) {
    __shared__ float sW21[HH * HH], sW22[HH * HH];
    __shared__ float sb21[HH], sb22[HH];
    __shared__ float sh[16][HH], st[16][HH];
    int tid = threadIdx.x;
    for (int i = tid; i < HH * HH; i += 256) { sW21[i] = W21[i]; sW22[i] = W22[i]; }
    if (tid < HH) { sb21[tid] = b21[tid]; sb22[tid] = b22[tid]; }
    __syncthreads();
    float epsv = 1.0f + __ldg(eps2);
    int q = tid & 15, nl = tid >> 4;
    int base = blockIdx.x * 80;
#pragma unroll
    for (int it = 0; it < 5; it++) {
        int node = base + it * 16 + nl;
        size_t off = (size_t)node * HH + q * 4;
        float4 h1v = __ldg((const float4*)(g_h1 + off));
        float4 ag  = *(const float4*)(g_agg2 + off);
        float4 hin;
        hin.x = fmaf(epsv, h1v.x, ag.x);
        hin.y = fmaf(epsv, h1v.y, ag.y);
        hin.z = fmaf(epsv, h1v.z, ag.z);
        hin.w = fmaf(epsv, h1v.w, ag.w);
        *(float4*)&sh[nl][q * 4] = hin;
        __syncwarp();
        // layer 1
        u64 a0 = pack2f(sb21[q * 4], sb21[q * 4 + 1]);
        u64 a1 = pack2f(sb21[q * 4 + 2], sb21[q * 4 + 3]);
#pragma unroll
        for (int j = 0; j < HH; j++) {
            u64 s2 = pack2(sh[nl][j]);
            ulonglong2 wv = *(const ulonglong2*)&sW21[j * HH + q * 4];
            a0 = fma2(wv.x, s2, a0);
            a1 = fma2(wv.y, s2, a1);
        }
        float2 lo = unpack2(a0), hi = unpack2(a1);
        float4 t;
        t.x = fmaxf(lo.x, 0.f); t.y = fmaxf(lo.y, 0.f);
        t.z = fmaxf(hi.x, 0.f); t.w = fmaxf(hi.y, 0.f);
        *(float4*)&st[nl][q * 4] = t;
        __syncwarp();
        // layer 2
        a0 = pack2f(sb22[q * 4], sb22[q * 4 + 1]);
        a1 = pack2f(sb22[q * 4 + 2], sb22[q * 4 + 3]);
#pragma unroll
        for (int j = 0; j < HH; j++) {
            u64 s2 = pack2(st[nl][j]);
            ulonglong2 wv = *(const ulonglong2*)&sW22[j * HH + q * 4];
            a0 = fma2(wv.x, s2, a0);
            a1 = fma2(wv.y, s2, a1);
        }
        lo = unpack2(a0); hi = unpack2(a1);
        float4 o;
        o.x = fmaxf(lo.x, 0.f); o.y = fmaxf(lo.y, 0.f);
        o.z = fmaxf(hi.x, 0.f); o.w = fmaxf(hi.y, 0.f);
        *(float4*)(g_h2 + off) = o;
        __syncwarp();
    }
}

// heads: 16 thr/node (thread q owns latent dims 2q,2q+1 of both mu and lv),
// 80 nodes/block (grid 1250); pooled sums run-length-accumulated (batch sorted).
__global__ __launch_bounds__(256) void k_heads(const float* __restrict__ Wmu,
                                               const float* __restrict__ bmu,
                                               const float* __restrict__ Wlv,
                                               const float* __restrict__ blv,
                                               const int*   __restrict__ batch,
                                               float* __restrict__ out) {
    __shared__ float sWmu[HH * LL], sWlv[HH * LL];
    __shared__ float sbmu[LL], sblv[LL];
    __shared__ float sh2[16][HH];
    __shared__ int   sb[80];
    int tid = threadIdx.x;
    int base = blockIdx.x * 80;
    for (int i = tid; i < HH * LL; i += 256) { sWmu[i] = Wmu[i]; sWlv[i] = Wlv[i]; }
    if (tid < LL) { sbmu[tid] = bmu[tid]; sblv[tid] = blv[tid]; }
    if (tid < 80) sb[tid] = batch[base + tid];
    __syncthreads();
    int q = tid & 15, nl = tid >> 4;
    int l0 = q * 2;
    float* out_z  = out;
    float* out_mu = out + (size_t)NN * LL;
    float* out_lv = out + (size_t)2 * NN * LL;
    float2 accz = make_float2(0.f, 0.f);
    float accn = 0.f;
    int accb = -1;
#pragma unroll
    for (int it = 0; it < 5; it++) {
        int node = base + it * 16 + nl;
        float4 h = __ldg((const float4*)(g_h2 + (size_t)node * HH + q * 4));
        *(float4*)&sh2[nl][q * 4] = h;
        __syncwarp();
        u64 mu2 = pack2f(sbmu[l0], sbmu[l0 + 1]);
        u64 lv2 = pack2f(sblv[l0], sblv[l0 + 1]);
#pragma unroll
        for (int k = 0; k < HH; k++) {
            u64 s2 = pack2(sh2[nl][k]);
            u64 wm = *(const u64*)&sWmu[k * LL + l0];
            u64 wl = *(const u64*)&sWlv[k * LL + l0];
            mu2 = fma2(wm, s2, mu2);
            lv2 = fma2(wl, s2, lv2);
        }
        float2 mu = unpack2(mu2), lv = unpack2(lv2);
        uint32_t flat = (uint32_t)node * LL + (uint32_t)l0;
        float nz0 = jax_normal_42(flat);
        float nz1 = jax_normal_42(flat + 1u);
        float2 z;
        z.x = fmaf(nz0, expf(0.5f * lv.x), mu.x);
        z.y = fmaf(nz1, expf(0.5f * lv.y), mu.y);
        *(float2*)(out_z  + flat) = z;
        *(float2*)(out_mu + flat) = mu;
        *(float2*)(out_lv + flat) = lv;
        int b = sb[it * 16 + nl];
        if (b != accb) {
            if (accb >= 0) {
                red2(g_zsum + accb * LL + l0, accz);
                if (q == 0) atomicAdd(&g_cnt[accb], accn);
            }
            accb = b; accz = z; accn = 1.f;
        } else {
            accz.x += z.x; accz.y += z.y; accn += 1.f;
        }
        __syncwarp();
    }
    if (accb >= 0) {
        red2(g_zsum + accb * LL + l0, accz);
        if (q == 0) atomicAdd(&g_cnt[accb], accn);
    }
}

__global__ __launch_bounds__(256) void k_logits(const float* __restrict__ Wc,
                                                const float* __restrict__ bc,
                                                float* __restrict__ out) {
    int g = blockIdx.x * 256 + threadIdx.x;
    if (g >= GG) return;
    float inv = 1.0f / fmaxf(g_cnt[g], 1.0f);
    float acc[CC];
#pragma unroll
    for (int c = 0; c < CC; c++) acc[c] = __ldg(bc + c);
#pragma unroll
    for (int l = 0; l < LL; l++) {
        float v = g_zsum[g * LL + l] * inv;
#pragma unroll
        for (int c = 0; c < CC; c++) acc[c] = fmaf(v, __ldg(Wc + l * CC + c), acc[c]);
    }
    float* out_lg = out + (size_t)3 * NN * LL;
#pragma unroll
    for (int c = 0; c < CC; c++) out_lg[(size_t)g * CC + c] = acc[c];
}

// ---------------- launch -----------------------------------------------------
extern "C" void kernel_launch(void* const* d_in, const int* in_sizes, int n_in,
                              void* d_out, int out_size) {
    const float* x     = (const float*)d_in[0];
    const int*   ei    = (const int*)  d_in[1];
    const float* eattr = (const float*)d_in[2];
    const int*   batch = (const int*)  d_in[3];
    const float* We1  = (const float*)d_in[4];
    const float* be1  = (const float*)d_in[5];
    const float* W11  = (const float*)d_in[6];
    const float* b11  = (const float*)d_in[7];
    const float* W12  = (const float*)d_in[8];
    const float* b12  = (const float*)d_in[9];
    const float* eps1 = (const float*)d_in[10];
    const float* We2  = (const float*)d_in[11];
    const float* be2  = (const float*)d_in[12];
    const float* W21  = (const float*)d_in[13];
    const float* b21  = (const float*)d_in[14];
    const float* W22  = (const float*)d_in[15];
    const float* b22  = (const float*)d_in[16];
    const float* eps2 = (const float*)d_in[17];
    const float* Wmu  = (const float*)d_in[18];
    const float* bmu  = (const float*)d_in[19];
    const float* Wlv  = (const float*)d_in[20];
    const float* blv  = (const float*)d_in[21];
    const float* Wc   = (const float*)d_in[22];
    const float* bc   = (const float*)d_in[23];
    float* out = (float*)d_out;

    k_zero  <<<(NN * HH) / (4 * 256), 256>>>();                 // 6250 blocks
    k_edge1 <<<EE / 256, 256>>>(x, ei, eattr, We1, be1);        // 6250 blocks
    k_mlp1  <<<NN / 80, 256>>>(x, W11, b11, W12, b12, eps1);    // 1250 blocks
    k_edge2 <<<EE / 128, 256>>>(ei, eattr, We2, be2);           // 12500 blocks
    k_mlp2  <<<NN / 80, 256>>>(W21, b21, W22, b22, eps2);       // 1250 blocks
    k_heads <<<NN / 80, 256>>>(Wmu, bmu, Wlv, blv, batch, out); // 1250 blocks
    k_logits<<<(GG + 255) / 256, 256>>>(Wc, bc, out);
}

// round 12
// speedup vs baseline: 2.1128x; 1.5645x over previous
#include <cuda_runtime.h>
#include <cstdint>

#define NN 100000
#define EE 1600000
#define EA 7
#define HH 64
#define LL 32
#define GG 512
#define CC 6

// ---------------- scratch (static device globals: no allocation) -------------
__device__ float g_agg1[NN];
__device__ float g_h1[(size_t)NN * HH];
__device__ float g_agg2[(size_t)NN * HH];
__device__ float g_h2[(size_t)NN * HH];
__device__ float g_zsum[GG * LL];
__device__ float g_cnt[GG];

// ---------------- f32x2 / vector-red helpers ---------------------------------
typedef unsigned long long u64;
__device__ __forceinline__ u64 pack2f(float x, float y) {
    u64 r; asm("mov.b64 %0,{%1,%2};" : "=l"(r) : "f"(x), "f"(y)); return r;
}
__device__ __forceinline__ u64 pack2(float x) {
    u64 r; asm("mov.b64 %0,{%1,%1};" : "=l"(r) : "f"(x)); return r;
}
__device__ __forceinline__ float2 unpack2(u64 v) {
    float2 f; asm("mov.b64 {%0,%1},%2;" : "=f"(f.x), "=f"(f.y) : "l"(v)); return f;
}
__device__ __forceinline__ u64 fma2(u64 a, u64 b, u64 c) {
    u64 d; asm("fma.rn.f32x2 %0,%1,%2,%3;" : "=l"(d) : "l"(a), "l"(b), "l"(c)); return d;
}
__device__ __forceinline__ void red4(float* p, float4 v) {
    asm volatile("red.global.add.v4.f32 [%0],{%1,%2,%3,%4};"
                 :: "l"(p), "f"(v.x), "f"(v.y), "f"(v.z), "f"(v.w) : "memory");
}
__device__ __forceinline__ void red2(float* p, float2 v) {
    asm volatile("red.global.add.v2.f32 [%0],{%1,%2};"
                 :: "l"(p), "f"(v.x), "f"(v.y) : "memory");
}

// ---------------- JAX threefry2x32-20 (partitionable) + normal ----------------
__device__ __forceinline__ void tf_round(uint32_t& x0, uint32_t& x1, int r) {
    x0 += x1;
    x1 = (x1 << r) | (x1 >> (32 - r));
    x1 ^= x0;
}
__device__ __forceinline__ void threefry2x32(uint32_t k0, uint32_t k1,
                                             uint32_t c0, uint32_t c1,
                                             uint32_t& o0, uint32_t& o1) {
    uint32_t ks2 = k0 ^ k1 ^ 0x1BD11BDAu;
    uint32_t x0 = c0 + k0, x1 = c1 + k1;
    tf_round(x0,x1,13); tf_round(x0,x1,15); tf_round(x0,x1,26); tf_round(x0,x1,6);
    x0 += k1;  x1 += ks2 + 1u;
    tf_round(x0,x1,17); tf_round(x0,x1,29); tf_round(x0,x1,16); tf_round(x0,x1,24);
    x0 += ks2; x1 += k0 + 2u;
    tf_round(x0,x1,13); tf_round(x0,x1,15); tf_round(x0,x1,26); tf_round(x0,x1,6);
    x0 += k0;  x1 += k1 + 3u;
    tf_round(x0,x1,17); tf_round(x0,x1,29); tf_round(x0,x1,16); tf_round(x0,x1,24);
    x0 += k1;  x1 += ks2 + 4u;
    tf_round(x0,x1,13); tf_round(x0,x1,15); tf_round(x0,x1,26); tf_round(x0,x1,6);
    x0 += ks2; x1 += k0 + 5u;
    o0 = x0; o1 = x1;
}
__device__ __forceinline__ float jax_normal_42(uint32_t flat) {
    uint32_t o0, o1;
    threefry2x32(0u, 42u, 0u, flat, o0, o1);
    uint32_t bits = o0 ^ o1;
    float f = __uint_as_float((bits >> 9) | 0x3F800000u) - 1.0f;   // [0,1)
    const float lo = -0.99999994f;
    float u = fmaf(f, 1.0f - lo, lo);
    u = fmaxf(u, lo);
    return 1.41421356f * erfinvf(u);
}

// ---------------- kernels ----------------------------------------------------

// zero agg1 + zsum + cnt (agg2 zeroed inside k_mlp1)
__global__ __launch_bounds__(256) void k_zero() {            // grid 98
    int i = blockIdx.x * 256 + threadIdx.x;
    float4 z = make_float4(0.f, 0.f, 0.f, 0.f);
    if (i < NN / 4)      ((float4*)g_agg1)[i] = z;
    if (i < GG * LL / 4) ((float4*)g_zsum)[i] = z;
    if (i < GG / 4)      ((float4*)g_cnt)[i]  = z;
}

// edge pass 1 (scalar features); eattr staged via smem. 256 edges/block.
__global__ __launch_bounds__(256) void k_edge1(const float* __restrict__ x,
                                               const int*   __restrict__ ei,
                                               const float* __restrict__ eattr,
                                               const float* __restrict__ We1,
                                               const float* __restrict__ be1) {
    __shared__ float sea[256 * EA];
    int tid = threadIdx.x;
    size_t base = (size_t)blockIdx.x * 256;
    for (int i = tid; i < 256 * EA; i += 256) sea[i] = eattr[base * EA + i];
    float rW[EA];
#pragma unroll
    for (int a = 0; a < EA; a++) rW[a] = __ldg(We1 + a);
    float rbe = __ldg(be1);
    __syncthreads();
    size_t e = base + tid;
    int s = ei[e], d = ei[EE + e];
    float v = rbe;
#pragma unroll
    for (int a = 0; a < EA; a++) v = fmaf(sea[tid * EA + a], rW[a], v);
    float m = fmaxf(x[s] + v, 0.f);
    atomicAdd(&g_agg1[d], m);
}

// node MLP 1: 16 thr/node-group, 5 nodes per group, 80 nodes/block (grid 1250).
// Also zeroes g_agg2 for its nodes (before k_edge2 runs).
__global__ __launch_bounds__(256) void k_mlp1(const float* __restrict__ x,
                                              const float* __restrict__ W11,
                                              const float* __restrict__ b11,
                                              const float* __restrict__ W12,
                                              const float* __restrict__ b12,
                                              const float* __restrict__ eps1) {
    __shared__ float sh[16][5][68];
    int tid = threadIdx.x;
    int q = tid & 15, nl = tid >> 4;
    int base = blockIdx.x * 80 + nl * 5;
    float epsv = 1.0f + __ldg(eps1);
    float4 w11 = __ldg((const float4*)(W11 + q * 4));
    float4 b1v = __ldg((const float4*)(b11 + q * 4));
    const float4 zf4 = make_float4(0.f, 0.f, 0.f, 0.f);
    // layer 1 (outer product) + zero agg2
#pragma unroll
    for (int n = 0; n < 5; n++) {
        int node = base + n;
        size_t off = (size_t)node * HH + q * 4;
        *(float4*)(g_agg2 + off) = zf4;
        float hx = fmaf(epsv, __ldg(x + node), g_agg1[node]);
        float4 t;
        t.x = fmaxf(fmaf(hx, w11.x, b1v.x), 0.f);
        t.y = fmaxf(fmaf(hx, w11.y, b1v.y), 0.f);
        t.z = fmaxf(fmaf(hx, w11.z, b1v.z), 0.f);
        t.w = fmaxf(fmaf(hx, w11.w, b1v.w), 0.f);
        *(float4*)&sh[nl][n][q * 4] = t;
    }
    __syncwarp();
    // layer 2: weights via __ldg (L1-resident), amortized over 5 nodes
    float4 b2v = __ldg((const float4*)(b12 + q * 4));
    u64 a0[5], a1[5];
#pragma unroll
    for (int n = 0; n < 5; n++) { a0[n] = pack2f(b2v.x, b2v.y); a1[n] = pack2f(b2v.z, b2v.w); }
#pragma unroll
    for (int j4 = 0; j4 < 16; j4++) {
        float4 w0 = __ldg((const float4*)(W12 + (j4 * 4 + 0) * HH + q * 4));
        float4 w1 = __ldg((const float4*)(W12 + (j4 * 4 + 1) * HH + q * 4));
        float4 w2 = __ldg((const float4*)(W12 + (j4 * 4 + 2) * HH + q * 4));
        float4 w3 = __ldg((const float4*)(W12 + (j4 * 4 + 3) * HH + q * 4));
#pragma unroll
        for (int n = 0; n < 5; n++) {
            float4 hv = *(const float4*)&sh[nl][n][j4 * 4];
            a0[n] = fma2(pack2f(w0.x, w0.y), pack2(hv.x), a0[n]);
            a1[n] = fma2(pack2f(w0.z, w0.w), pack2(hv.x), a1[n]);
            a0[n] = fma2(pack2f(w1.x, w1.y), pack2(hv.y), a0[n]);
            a1[n] = fma2(pack2f(w1.z, w1.w), pack2(hv.y), a1[n]);
            a0[n] = fma2(pack2f(w2.x, w2.y), pack2(hv.z), a0[n]);
            a1[n] = fma2(pack2f(w2.z, w2.w), pack2(hv.z), a1[n]);
            a0[n] = fma2(pack2f(w3.x, w3.y), pack2(hv.w), a0[n]);
            a1[n] = fma2(pack2f(w3.z, w3.w), pack2(hv.w), a1[n]);
        }
    }
#pragma unroll
    for (int n = 0; n < 5; n++) {
        float2 lo = unpack2(a0[n]), hi = unpack2(a1[n]);
        float4 o;
        o.x = fmaxf(lo.x, 0.f); o.y = fmaxf(lo.y, 0.f);
        o.z = fmaxf(hi.x, 0.f); o.w = fmaxf(hi.y, 0.f);
        *(float4*)(g_h1 + (size_t)(base + n) * HH + q * 4) = o;
    }
}

// edge pass 2: 128 edges/block (grid 12500), 16 thr/edge, float4 + red.v4
__global__ __launch_bounds__(256) void k_edge2(const int*   __restrict__ ei,
                                               const float* __restrict__ eattr,
                                               const float* __restrict__ We2,
                                               const float* __restrict__ be2) {
    __shared__ float sea[128 * EA];
    __shared__ int   ss[128], sd[128];
    int tid = threadIdx.x;
    size_t base = (size_t)blockIdx.x * 128;
    for (int i = tid; i < 128 * EA; i += 256) sea[i] = eattr[base * EA + i];
    if (tid < 128)       ss[tid] = ei[base + tid];
    else                 sd[tid - 128] = ei[EE + base + (tid - 128)];
    int q = tid & 15, el = tid >> 4;
    ulonglong2 rw[EA];
#pragma unroll
    for (int a = 0; a < EA; a++) {
        float4 w = __ldg((const float4*)(We2 + a * HH + q * 4));
        rw[a].x = pack2f(w.x, w.y);
        rw[a].y = pack2f(w.z, w.w);
    }
    float4 rb = __ldg((const float4*)(be2 + q * 4));
    u64 rb0 = pack2f(rb.x, rb.y), rb1 = pack2f(rb.z, rb.w);
    __syncthreads();
#pragma unroll 2
    for (int sub = 0; sub < 8; sub++) {
        int e = sub * 16 + el;
        int s = ss[e], d = sd[e];
        float4 h = __ldg((const float4*)(g_h1 + (size_t)s * HH + q * 4));
        u64 v0 = rb0, v1 = rb1;
#pragma unroll
        for (int a = 0; a < EA; a++) {
            u64 ea2 = pack2(sea[e * EA + a]);
            v0 = fma2(rw[a].x, ea2, v0);
            v1 = fma2(rw[a].y, ea2, v1);
        }
        float2 lo = unpack2(v0), hi = unpack2(v1);
        float4 m;
        m.x = fmaxf(h.x + lo.x, 0.f);
        m.y = fmaxf(h.y + lo.y, 0.f);
        m.z = fmaxf(h.z + hi.x, 0.f);
        m.w = fmaxf(h.w + hi.y, 0.f);
        red4(g_agg2 + (size_t)d * HH + q * 4, m);
    }
}

// node MLP 2: 16 thr/group, 5 nodes/group, 80 nodes/block (grid 1250)
__global__ __launch_bounds__(256) void k_mlp2(const float* __restrict__ W21,
                                              const float* __restrict__ b21,
                                              const float* __restrict__ W22,
                                              const float* __restrict__ b22,
                                              const float* __restrict__ eps2) {
    __shared__ float sh[16][5][68];
    int tid = threadIdx.x;
    int q = tid & 15, nl = tid >> 4;
    int base = blockIdx.x * 80 + nl * 5;
    float epsv = 1.0f + __ldg(eps2);
    // stage h_in = (1+eps)*h1 + agg2
#pragma unroll
    for (int n = 0; n < 5; n++) {
        size_t off = (size_t)(base + n) * HH + q * 4;
        float4 h1v = __ldg((const float4*)(g_h1 + off));
        float4 ag  = *(const float4*)(g_agg2 + off);
        float4 hin;
        hin.x = fmaf(epsv, h1v.x, ag.x);
        hin.y = fmaf(epsv, h1v.y, ag.y);
        hin.z = fmaf(epsv, h1v.z, ag.z);
        hin.w = fmaf(epsv, h1v.w, ag.w);
        *(float4*)&sh[nl][n][q * 4] = hin;
    }
    __syncwarp();
    u64 a0[5], a1[5];
    // ---- layer 1 ----
    {
        float4 bv = __ldg((const float4*)(b21 + q * 4));
#pragma unroll
        for (int n = 0; n < 5; n++) { a0[n] = pack2f(bv.x, bv.y); a1[n] = pack2f(bv.z, bv.w); }
#pragma unroll
        for (int j4 = 0; j4 < 16; j4++) {
            float4 w0 = __ldg((const float4*)(W21 + (j4 * 4 + 0) * HH + q * 4));
            float4 w1 = __ldg((const float4*)(W21 + (j4 * 4 + 1) * HH + q * 4));
            float4 w2 = __ldg((const float4*)(W21 + (j4 * 4 + 2) * HH + q * 4));
            float4 w3 = __ldg((const float4*)(W21 + (j4 * 4 + 3) * HH + q * 4));
#pragma unroll
            for (int n = 0; n < 5; n++) {
                float4 hv = *(const float4*)&sh[nl][n][j4 * 4];
                a0[n] = fma2(pack2f(w0.x, w0.y), pack2(hv.x), a0[n]);
                a1[n] = fma2(pack2f(w0.z, w0.w), pack2(hv.x), a1[n]);
                a0[n] = fma2(pack2f(w1.x, w1.y), pack2(hv.y), a0[n]);
                a1[n] = fma2(pack2f(w1.z, w1.w), pack2(hv.y), a1[n]);
                a0[n] = fma2(pack2f(w2.x, w2.y), pack2(hv.z), a0[n]);
                a1[n] = fma2(pack2f(w2.z, w2.w), pack2(hv.z), a1[n]);
                a0[n] = fma2(pack2f(w3.x, w3.y), pack2(hv.w), a0[n]);
                a1[n] = fma2(pack2f(w3.z, w3.w), pack2(hv.w), a1[n]);
            }
        }
        __syncwarp();
#pragma unroll
        for (int n = 0; n < 5; n++) {
            float2 lo = unpack2(a0[n]), hi = unpack2(a1[n]);
            float4 t;
            t.x = fmaxf(lo.x, 0.f); t.y = fmaxf(lo.y, 0.f);
            t.z = fmaxf(hi.x, 0.f); t.w = fmaxf(hi.y, 0.f);
            *(float4*)&sh[nl][n][q * 4] = t;
        }
        __syncwarp();
    }
    // ---- layer 2 ----
    {
        float4 bv = __ldg((const float4*)(b22 + q * 4));
#pragma unroll
        for (int n = 0; n < 5; n++) { a0[n] = pack2f(bv.x, bv.y); a1[n] = pack2f(bv.z, bv.w); }
#pragma unroll
        for (int j4 = 0; j4 < 16; j4++) {
            float4 w0 = __ldg((const float4*)(W22 + (j4 * 4 + 0) * HH + q * 4));
            float4 w1 = __ldg((const float4*)(W22 + (j4 * 4 + 1) * HH + q * 4));
            float4 w2 = __ldg((const float4*)(W22 + (j4 * 4 + 2) * HH + q * 4));
            float4 w3 = __ldg((const float4*)(W22 + (j4 * 4 + 3) * HH + q * 4));
#pragma unroll
            for (int n = 0; n < 5; n++) {
                float4 hv = *(const float4*)&sh[nl][n][j4 * 4];
                a0[n] = fma2(pack2f(w0.x, w0.y), pack2(hv.x), a0[n]);
                a1[n] = fma2(pack2f(w0.z, w0.w), pack2(hv.x), a1[n]);
                a0[n] = fma2(pack2f(w1.x, w1.y), pack2(hv.y), a0[n]);
                a1[n] = fma2(pack2f(w1.z, w1.w), pack2(hv.y), a1[n]);
                a0[n] = fma2(pack2f(w2.x, w2.y), pack2(hv.z), a0[n]);
                a1[n] = fma2(pack2f(w2.z, w2.w), pack2(hv.z), a1[n]);
                a0[n] = fma2(pack2f(w3.x, w3.y), pack2(hv.w), a0[n]);
                a1[n] = fma2(pack2f(w3.z, w3.w), pack2(hv.w), a1[n]);
            }
        }
#pragma unroll
        for (int n = 0; n < 5; n++) {
            float2 lo = unpack2(a0[n]), hi = unpack2(a1[n]);
            float4 o;
            o.x = fmaxf(lo.x, 0.f); o.y = fmaxf(lo.y, 0.f);
            o.z = fmaxf(hi.x, 0.f); o.w = fmaxf(hi.y, 0.f);
            *(float4*)(g_h2 + (size_t)(base + n) * HH + q * 4) = o;
        }
    }
}

// heads: 16 thr/group, 5 nodes/group; thread q owns latent dims 2q,2q+1.
// pooled sums run-length-accumulated (batch sorted, nodes consecutive per group).
__global__ __launch_bounds__(256) void k_heads(const float* __restrict__ Wmu,
                                               const float* __restrict__ bmu,
                                               const float* __restrict__ Wlv,
                                               const float* __restrict__ blv,
                                               const int*   __restrict__ batch,
                                               float* __restrict__ out) {
    __shared__ float sh[16][5][68];
    int tid = threadIdx.x;
    int q = tid & 15, nl = tid >> 4;
    int base = blockIdx.x * 80 + nl * 5;
    int l0 = q * 2;
#pragma unroll
    for (int n = 0; n < 5; n++) {
        float4 h = __ldg((const float4*)(g_h2 + (size_t)(base + n) * HH + q * 4));
        *(float4*)&sh[nl][n][q * 4] = h;
    }
    __syncwarp();
    u64 amu[5], alv[5];
    u64 bm = *(const u64*)(bmu + l0);
    u64 bl = *(const u64*)(blv + l0);
#pragma unroll
    for (int n = 0; n < 5; n++) { amu[n] = bm; alv[n] = bl; }
#pragma unroll
    for (int j4 = 0; j4 < 16; j4++) {
        u64 wm0 = __ldg((const u64*)(Wmu + (j4 * 4 + 0) * LL + l0));
        u64 wm1 = __ldg((const u64*)(Wmu + (j4 * 4 + 1) * LL + l0));
        u64 wm2 = __ldg((const u64*)(Wmu + (j4 * 4 + 2) * LL + l0));
        u64 wm3 = __ldg((const u64*)(Wmu + (j4 * 4 + 3) * LL + l0));
        u64 wl0 = __ldg((const u64*)(Wlv + (j4 * 4 + 0) * LL + l0));
        u64 wl1 = __ldg((const u64*)(Wlv + (j4 * 4 + 1) * LL + l0));
        u64 wl2 = __ldg((const u64*)(Wlv + (j4 * 4 + 2) * LL + l0));
        u64 wl3 = __ldg((const u64*)(Wlv + (j4 * 4 + 3) * LL + l0));
#pragma unroll
        for (int n = 0; n < 5; n++) {
            float4 hv = *(const float4*)&sh[nl][n][j4 * 4];
            u64 h0 = pack2(hv.x), h1 = pack2(hv.y), h2 = pack2(hv.z), h3 = pack2(hv.w);
            amu[n] = fma2(wm0, h0, amu[n]);
            alv[n] = fma2(wl0, h0, alv[n]);
            amu[n] = fma2(wm1, h1, amu[n]);
            alv[n] = fma2(wl1, h1, alv[n]);
            amu[n] = fma2(wm2, h2, amu[n]);
            alv[n] = fma2(wl2, h2, alv[n]);
            amu[n] = fma2(wm3, h3, amu[n]);
            alv[n] = fma2(wl3, h3, alv[n]);
        }
    }
    float* out_z  = out;
    float* out_mu = out + (size_t)NN * LL;
    float* out_lv = out + (size_t)2 * NN * LL;
    float2 accz = make_float2(0.f, 0.f);
    float accn = 0.f;
    int accb = -1;
#pragma unroll
    for (int n = 0; n < 5; n++) {
        int node = base + n;
        float2 mu = unpack2(amu[n]), lv = unpack2(alv[n]);
        uint32_t flat = (uint32_t)node * LL + (uint32_t)l0;
        float nz0 = jax_normal_42(flat);
        float nz1 = jax_normal_42(flat + 1u);
        float2 z;
        z.x = fmaf(nz0, expf(0.5f * lv.x), mu.x);
        z.y = fmaf(nz1, expf(0.5f * lv.y), mu.y);
        *(float2*)(out_z  + flat) = z;
        *(float2*)(out_mu + flat) = mu;
        *(float2*)(out_lv + flat) = lv;
        int b = __ldg(batch + node);
        if (b != accb) {
            if (accb >= 0) {
                red2(g_zsum + accb * LL + l0, accz);
                if (q == 0) atomicAdd(&g_cnt[accb], accn);
            }
            accb = b; accz = z; accn = 1.f;
        } else {
            accz.x += z.x; accz.y += z.y; accn += 1.f;
        }
    }
    if (accb >= 0) {
        red2(g_zsum + accb * LL + l0, accz);
        if (q == 0) atomicAdd(&g_cnt[accb], accn);
    }
}

__global__ __launch_bounds__(256) void k_logits(const float* __restrict__ Wc,
                                                const float* __restrict__ bc,
                                                float* __restrict__ out) {
    int g = blockIdx.x * 256 + threadIdx.x;
    if (g >= GG) return;
    float inv = 1.0f / fmaxf(g_cnt[g], 1.0f);
    float acc[CC];
#pragma unroll
    for (int c = 0; c < CC; c++) acc[c] = __ldg(bc + c);
#pragma unroll
    for (int l = 0; l < LL; l++) {
        float v = g_zsum[g * LL + l] * inv;
#pragma unroll
        for (int c = 0; c < CC; c++) acc[c] = fmaf(v, __ldg(Wc + l * CC + c), acc[c]);
    }
    float* out_lg = out + (size_t)3 * NN * LL;
#pragma unroll
    for (int c = 0; c < CC; c++) out_lg[(size_t)g * CC + c] = acc[c];
}

// ---------------- launch -----------------------------------------------------
extern "C" void kernel_launch(void* const* d_in, const int* in_sizes, int n_in,
                              void* d_out, int out_size) {
    const float* x     = (const float*)d_in[0];
    const int*   ei    = (const int*)  d_in[1];
    const float* eattr = (const float*)d_in[2];
    const int*   batch = (const int*)  d_in[3];
    const float* We1  = (const float*)d_in[4];
    const float* be1  = (const float*)d_in[5];
    const float* W11  = (const float*)d_in[6];
    const float* b11  = (const float*)d_in[7];
    const float* W12  = (const float*)d_in[8];
    const float* b12  = (const float*)d_in[9];
    const float* eps1 = (const float*)d_in[10];
    const float* We2  = (const float*)d_in[11];
    const float* be2  = (const float*)d_in[12];
    const float* W21  = (const float*)d_in[13];
    const float* b21  = (const float*)d_in[14];
    const float* W22  = (const float*)d_in[15];
    const float* b22  = (const float*)d_in[16];
    const float* eps2 = (const float*)d_in[17];
    const float* Wmu  = (const float*)d_in[18];
    const float* bmu  = (const float*)d_in[19];
    const float* Wlv  = (const float*)d_in[20];
    const float* blv  = (const float*)d_in[21];
    const float* Wc   = (const float*)d_in[22];
    const float* bc   = (const float*)d_in[23];
    float* out = (float*)d_out;

    k_zero  <<<98, 256>>>();                                    // agg1+zsum+cnt
    k_edge1 <<<EE / 256, 256>>>(x, ei, eattr, We1, be1);        // 6250 blocks
    k_mlp1  <<<NN / 80, 256>>>(x, W11, b11, W12, b12, eps1);    // 1250 blocks (+agg2 zero)
    k_edge2 <<<EE / 128, 256>>>(ei, eattr, We2, be2);           // 12500 blocks
    k_mlp2  <<<NN / 80, 256>>>(W21, b21, W22, b22, eps2);       // 1250 blocks
    k_heads <<<NN / 80, 256>>>(Wmu, bmu, Wlv, blv, batch, out); // 1250 blocks
    k_logits<<<2, 256>>>(Wc, bc, out);
}